// round 6
// baseline (speedup 1.0000x reference)
#include <cuda_runtime.h>
#include <cuda_fp16.h>
#include <cstdint>

// Problem constants
#define B_   4
#define N_   4096
#define D_   1024
#define H_   16
#define DH_  64
#define L_   64
#define NCH_ (N_ / L_)
#define M_   (B_ * N_)           // 16384 tokens

// Scratch (__device__ globals; no allocation allowed)
__device__ float g_carry[B_ * NCH_ * D_];
__device__ float g_lam[H_];
__device__ float g_c[H_];
__device__ __half g_a[M_ * D_];              // fp16 activations (post-norm)
__device__ __half g_w_hi[D_ * D_];           // o_w fp16 split
__device__ __half g_w_lo[D_ * D_];

__device__ __forceinline__ float pow_int(float base, int e) {
    float p = 1.0f, b = base;
    while (e) { if (e & 1) p *= b; b *= b; e >>= 1; }
    return p;
}

__device__ __forceinline__ uint32_t smem_u32(const void* p) {
    uint32_t a;
    asm("{ .reg .u64 t; cvta.to.shared.u64 t, %1; cvt.u32.u64 %0, t; }" : "=r"(a) : "l"(p));
    return a;
}

#define CP_ASYNC16(dst, src) \
    asm volatile("cp.async.cg.shared.global [%0], [%1], 16;" :: "r"(dst), "l"(src) : "memory")
#define CP_COMMIT() asm volatile("cp.async.commit_group;" ::: "memory")
#define CP_WAIT1()  asm volatile("cp.async.wait_group 1;" ::: "memory")

#define LDSM4(r0, r1, r2, r3, addr) \
    asm volatile("ldmatrix.sync.aligned.m8n8.x4.shared.b16 {%0,%1,%2,%3}, [%4];" \
                 : "=r"(r0), "=r"(r1), "=r"(r2), "=r"(r3) : "r"(addr))

#define MMA_F16(d, a, b) \
    asm volatile("mma.sync.aligned.m16n8k16.row.col.f32.f16.f16.f32 " \
                 "{%0,%1,%2,%3}, {%4,%5,%6,%7}, {%8,%9}, {%0,%1,%2,%3};" \
                 : "+f"((d)[0]), "+f"((d)[1]), "+f"((d)[2]), "+f"((d)[3]) \
                 : "r"((a)[0]), "r"((a)[1]), "r"((a)[2]), "r"((a)[3]), \
                   "r"((b)[0]), "r"((b)[1]))

// ============================ scan phases ============================
__global__ void k_init(const float* __restrict__ q, const float* __restrict__ k,
                       const float* __restrict__ log_decay) {
    int h = threadIdx.x;
    if (h >= H_) return;
    float a = log_decay[h];
    g_lam[h] = 1.0f / (1.0f + expf(-a));
    float c = 0.0f;
    const float* qh = q + h * DH_;
    const float* kh = k + h * DH_;
    #pragma unroll 16
    for (int j = 0; j < DH_; j++) c += qh[j] * kh[j];
    g_c[h] = c;
}

// Phase A: per-chunk carries only (no per-token output)
__global__ __launch_bounds__(1024) void k_scan_carries(const float* __restrict__ x) {
    int blk = blockIdx.x;
    int b = blk / NCH_;
    int c = blk % NCH_;
    int d = threadIdx.x;
    float lam = g_lam[d >> 6];
    size_t base = (size_t)(b * N_ + c * L_) * D_ + d;
    float s = 0.0f;
    #pragma unroll 8
    for (int t = 0; t < L_; t++) s = fmaf(lam, s, x[base + (size_t)t * D_]);
    g_carry[(b * NCH_ + c) * D_ + d] = s;
}

// Phase B: sequential combine across chunks (batched loads for MLP)
__global__ __launch_bounds__(256) void k_scan_combine() {
    int idx = blockIdx.x * blockDim.x + threadIdx.x;   // [0, B*D)
    int b = idx / D_;
    int d = idx % D_;
    float lam = g_lam[d >> 6];
    float lamL = pow_int(lam, L_);
    int base = b * NCH_ * D_ + d;

    float v[NCH_];
    #pragma unroll
    for (int c = 0; c < NCH_; c++) v[c] = g_carry[base + c * D_];
    float P = 0.0f;
    #pragma unroll
    for (int c = 0; c < NCH_; c++) { P = fmaf(lamL, P, v[c]); v[c] = P; }
    #pragma unroll
    for (int c = 0; c < NCH_; c++) g_carry[base + c * D_] = v[c];
}

// Phase C (fused): re-scan chunk with global carry as initial state, scale by
// c_h, RMSNorm per token, write fp16. One block per (b, chunk), 1024 threads.
// Processes 32 tokens per half (128KB fp32 staging in dynamic smem).
#define SNORM_SMEM (32 * 1024 * 4 + 256)
__global__ __launch_bounds__(1024) void k_scan_norm(const float* __restrict__ x,
                                                    const float* __restrict__ norm_weight) {
    extern __shared__ float sv[];                    // [32][1024]
    float* s_rstd = sv + 32 * 1024;                  // [32]
    int blk = blockIdx.x;
    int b = blk / NCH_;
    int c = blk % NCH_;
    int d = threadIdx.x;
    int lane = d & 31, wrp = d >> 5;
    float lam = g_lam[d >> 6];
    float ch  = g_c[d >> 6];
    float nw  = norm_weight[d];

    float s = (c > 0) ? g_carry[(b * NCH_ + (c - 1)) * D_ + d] : 0.0f;
    size_t xbase = (size_t)(b * N_ + c * L_) * D_ + d;

    #pragma unroll
    for (int half = 0; half < 2; half++) {
        // scan 32 tokens, stage c_h-scaled values in smem
        #pragma unroll 8
        for (int t = 0; t < 32; t++) {
            s = fmaf(lam, s, x[xbase + (size_t)(half * 32 + t) * D_]);
            sv[t * 1024 + d] = s * ch;
        }
        __syncthreads();
        // warp w reduces token w: 1024 values, lane-consecutive loads
        {
            float ss = 0.0f;
            const float* row = sv + wrp * 1024;
            #pragma unroll
            for (int j = 0; j < 32; j++) {
                float vv = row[lane + 32 * j];
                ss = fmaf(vv, vv, ss);
            }
            #pragma unroll
            for (int o = 16; o > 0; o >>= 1) ss += __shfl_xor_sync(0xFFFFFFFFu, ss, o);
            if (lane == 0) s_rstd[wrp] = rsqrtf(ss * (1.0f / (float)D_) + 1e-6f);
        }
        __syncthreads();
        // normalize + write fp16 (pack pairs via shfl -> 4B stores)
        int tok0 = (b * N_ + c * L_ + half * 32);
        #pragma unroll 4
        for (int t = 0; t < 32; t++) {
            float a = sv[t * 1024 + d] * s_rstd[t] * nw;
            float a1 = __shfl_down_sync(0xFFFFFFFFu, a, 1);
            if (!(d & 1)) {
                __half2 p = __floats2half2_rn(a, a1);
                *(__half2*)&g_a[(size_t)(tok0 + t) * D_ + d] = p;
            }
        }
        __syncthreads();
    }
}

__global__ __launch_bounds__(256) void k_prep_w(const float* __restrict__ w) {
    int idx = blockIdx.x * blockDim.x + threadIdx.x;
    size_t off = (size_t)idx * 4;
    float4 v = *(const float4*)&w[off];
    __half h0 = __float2half_rn(v.x), h1 = __float2half_rn(v.y);
    __half h2 = __float2half_rn(v.z), h3 = __float2half_rn(v.w);
    __half l0 = __float2half_rn(v.x - __half2float(h0));
    __half l1 = __float2half_rn(v.y - __half2float(h1));
    __half l2 = __float2half_rn(v.z - __half2float(h2));
    __half l3 = __float2half_rn(v.w - __half2float(h3));
    __half2 ph0; ph0.x = h0; ph0.y = h1;
    __half2 ph1; ph1.x = h2; ph1.y = h3;
    __half2 pl0; pl0.x = l0; pl0.y = l1;
    __half2 pl1; pl1.x = l2; pl1.y = l3;
    *(__half2*)&g_w_hi[off]     = ph0;
    *(__half2*)&g_w_hi[off + 2] = ph1;
    *(__half2*)&g_w_lo[off]     = pl0;
    *(__half2*)&g_w_lo[off + 2] = pl1;
}

// ============================ HMMA GEMM ============================
// C = A * (Whi + Wlo)^T. CTA tile 256x128, BK=64, 8 warps (4m x 2n),
// warp tile 64x64. STG=3 x 64KB stages.
#define GM 256
#define GN 128
#define KS 64
#define STG 3
#define NITER 16
#define A_TILE_B 32768                          // 256x64 fp16
#define W_TILE_B 16384                          // 128x64 fp16
#define STAGE_BYTES (A_TILE_B + 2 * W_TILE_B)   // 64KB
#define SMEM_GEMM_TOTAL (STG * STAGE_BYTES)     // 192KB

#define SMEM_SWZ(off) ((off) ^ (((off) >> 3) & 0x70))

__device__ __forceinline__ void load_stage(uint32_t smem_base, int round, int bm, int bn, int tid) {
    int k0 = round * KS;
    uint32_t st = smem_base + (round % STG) * STAGE_BYTES;
    // A: 2048 chunks; Whi: 1024; Wlo: 1024. 16 chunks per thread.
    #pragma unroll
    for (int i = 0; i < 16; i++) {
        int idx = i * 256 + tid;               // [0, 4096)
        if (idx < 2048) {                      // A: 256 rows x 8 chunks
            int r = idx >> 3, kc = idx & 7;
            const __half* g = g_a + (size_t)(bm + r) * D_ + k0 + kc * 8;
            CP_ASYNC16(st + SMEM_SWZ(r * 128 + kc * 16), g);
        } else {
            int c2 = idx - 2048;               // [0, 2048)
            int tile = c2 >> 10;               // 0:Whi 1:Wlo
            int c = c2 & 1023;
            int r = c >> 3, kc = c & 7;
            const __half* src = tile ? g_w_lo : g_w_hi;
            const __half* g = src + (size_t)(bn + r) * D_ + k0 + kc * 8;
            CP_ASYNC16(st + A_TILE_B + tile * W_TILE_B + SMEM_SWZ(r * 128 + kc * 16), g);
        }
    }
}

__global__ __launch_bounds__(256, 1) void k_gemm_mma(float* __restrict__ C) {
    extern __shared__ char smem[];
    uint32_t sb = smem_u32(smem);
    const int tid  = threadIdx.x;
    const int wid  = tid >> 5;
    const int lane = tid & 31;
    const int wm   = wid >> 1;          // 0..3 (M, x64)
    const int wn   = wid & 1;           // 0..1 (N, x64)
    const int bm   = blockIdx.y * GM;
    const int bn   = blockIdx.x * GN;

    const int t7 = lane & 7;
    const int q  = lane >> 3;
    // A x4 matrices: (m0,k0),(m+8,k0),(m0,k8),(m+8,k8)
    const int a_row = wm * 64 + (q & 1) * 8 + t7;
    const int a_cq  = q >> 1;
    // B x4 matrices: (n0,k0),(n0,k8),(n+8,k0),(n+8,k8)
    const int b_row = wn * 64 + (q >> 1) * 8 + t7;
    const int b_cq  = q & 1;

    float acc[4][8][4];
    #pragma unroll
    for (int im = 0; im < 4; im++)
        #pragma unroll
        for (int j = 0; j < 8; j++)
            #pragma unroll
            for (int e = 0; e < 4; e++) acc[im][j][e] = 0.0f;

    #pragma unroll
    for (int r = 0; r < STG - 1; r++) { load_stage(sb, r, bm, bn, tid); CP_COMMIT(); }

    for (int i = 0; i < NITER; i++) {
        CP_WAIT1();
        __syncthreads();
        int j = i + STG - 1;
        if (j < NITER) load_stage(sb, j, bm, bn, tid);
        CP_COMMIT();

        uint32_t st = sb + (i % STG) * STAGE_BYTES;
        #pragma unroll
        for (int ks = 0; ks < 4; ks++) {
            uint32_t af[4][4];
            #pragma unroll
            for (int im = 0; im < 4; im++) {
                uint32_t ro = (a_row + im * 16) * 128 + (((ks * 2 + a_cq) ^ t7) << 4);
                LDSM4(af[im][0], af[im][1], af[im][2], af[im][3], st + ro);
            }
            uint32_t bh[8][2], bl[8][2];
            #pragma unroll
            for (int jj = 0; jj < 4; jj++) {
                uint32_t ro = (b_row + jj * 16) * 128 + (((ks * 2 + b_cq) ^ t7) << 4);
                LDSM4(bh[2*jj][0], bh[2*jj][1], bh[2*jj+1][0], bh[2*jj+1][1],
                      st + A_TILE_B + ro);
                LDSM4(bl[2*jj][0], bl[2*jj][1], bl[2*jj+1][0], bl[2*jj+1][1],
                      st + A_TILE_B + W_TILE_B + ro);
            }
            #pragma unroll
            for (int im = 0; im < 4; im++)
                #pragma unroll
                for (int jt = 0; jt < 8; jt++) {
                    MMA_F16(acc[im][jt], af[im], bh[jt]);
                    MMA_F16(acc[im][jt], af[im], bl[jt]);
                }
        }
    }

    #pragma unroll
    for (int im = 0; im < 4; im++) {
        int r0 = bm + wm * 64 + im * 16 + (lane >> 2);
        #pragma unroll
        for (int jt = 0; jt < 8; jt++) {
            int c = bn + wn * 64 + jt * 8 + (lane & 3) * 2;
            *(float2*)&C[(size_t)r0 * D_ + c]       = make_float2(acc[im][jt][0], acc[im][jt][1]);
            *(float2*)&C[(size_t)(r0 + 8) * D_ + c] = make_float2(acc[im][jt][2], acc[im][jt][3]);
        }
    }
}

// ============================ launch ============================
extern "C" void kernel_launch(void* const* d_in, const int* in_sizes, int n_in,
                              void* d_out, int out_size) {
    const float* x           = (const float*)d_in[0];
    const float* q           = (const float*)d_in[1];
    const float* k           = (const float*)d_in[2];
    const float* log_decay   = (const float*)d_in[3];
    const float* norm_weight = (const float*)d_in[4];
    const float* o_w         = (const float*)d_in[5];
    float* out = (float*)d_out;

    k_init<<<1, 32>>>(q, k, log_decay);
    k_prep_w<<<(D_ * D_ / 4) / 256, 256>>>(o_w);
    k_scan_carries<<<B_ * NCH_, 1024>>>(x);
    k_scan_combine<<<(B_ * D_) / 256, 256>>>();

    cudaFuncSetAttribute(k_scan_norm, cudaFuncAttributeMaxDynamicSharedMemorySize, SNORM_SMEM);
    k_scan_norm<<<B_ * NCH_, 1024, SNORM_SMEM>>>(x, norm_weight);

    cudaFuncSetAttribute(k_gemm_mma, cudaFuncAttributeMaxDynamicSharedMemorySize,
                         SMEM_GEMM_TOTAL);
    dim3 grid(D_ / GN, M_ / GM);
    k_gemm_mma<<<grid, 256, SMEM_GEMM_TOTAL>>>(out);
}

// round 7
// speedup vs baseline: 1.0747x; 1.0747x over previous
#include <cuda_runtime.h>
#include <cuda_fp16.h>
#include <cstdint>

// Problem constants
#define B_   4
#define N_   4096
#define D_   1024
#define H_   16
#define DH_  64
#define L_   64
#define NCH_ (N_ / L_)
#define M_   (B_ * N_)           // 16384 tokens

// Scratch (__device__ globals; no allocation allowed)
__device__ float g_carry[B_ * NCH_ * D_];
__device__ float g_lam[H_];
__device__ float g_c[H_];
__device__ __half g_a[M_ * D_];              // fp16 activations (post-norm)
__device__ __half g_w_hi[D_ * D_];           // o_w fp16 split
__device__ __half g_w_lo[D_ * D_];

__device__ __forceinline__ float pow_int(float base, int e) {
    float p = 1.0f, b = base;
    while (e) { if (e & 1) p *= b; b *= b; e >>= 1; }
    return p;
}

__device__ __forceinline__ uint32_t smem_u32(const void* p) {
    uint32_t a;
    asm("{ .reg .u64 t; cvta.to.shared.u64 t, %1; cvt.u32.u64 %0, t; }" : "=r"(a) : "l"(p));
    return a;
}

#define CP_ASYNC16(dst, src) \
    asm volatile("cp.async.cg.shared.global [%0], [%1], 16;" :: "r"(dst), "l"(src) : "memory")
#define CP_COMMIT() asm volatile("cp.async.commit_group;" ::: "memory")
#define CP_WAIT1()  asm volatile("cp.async.wait_group 1;" ::: "memory")

#define LDSM4(r0, r1, r2, r3, addr) \
    asm volatile("ldmatrix.sync.aligned.m8n8.x4.shared.b16 {%0,%1,%2,%3}, [%4];" \
                 : "=r"(r0), "=r"(r1), "=r"(r2), "=r"(r3) : "r"(addr))

#define MMA_F16(d, a, b) \
    asm volatile("mma.sync.aligned.m16n8k16.row.col.f32.f16.f16.f32 " \
                 "{%0,%1,%2,%3}, {%4,%5,%6,%7}, {%8,%9}, {%0,%1,%2,%3};" \
                 : "+f"((d)[0]), "+f"((d)[1]), "+f"((d)[2]), "+f"((d)[3]) \
                 : "r"((a)[0]), "r"((a)[1]), "r"((a)[2]), "r"((a)[3]), \
                   "r"((b)[0]), "r"((b)[1]))

// ============================ scan phases ============================
__global__ void k_init(const float* __restrict__ q, const float* __restrict__ k,
                       const float* __restrict__ log_decay) {
    int h = threadIdx.x;
    if (h >= H_) return;
    float a = log_decay[h];
    g_lam[h] = 1.0f / (1.0f + expf(-a));
    float c = 0.0f;
    const float* qh = q + h * DH_;
    const float* kh = k + h * DH_;
    #pragma unroll 16
    for (int j = 0; j < DH_; j++) c += qh[j] * kh[j];
    g_c[h] = c;
}

// Phase A: per-chunk carries only
__global__ __launch_bounds__(1024) void k_scan_carries(const float* __restrict__ x) {
    int blk = blockIdx.x;
    int b = blk / NCH_;
    int c = blk % NCH_;
    int d = threadIdx.x;
    float lam = g_lam[d >> 6];
    size_t base = (size_t)(b * N_ + c * L_) * D_ + d;
    float s = 0.0f;
    #pragma unroll 8
    for (int t = 0; t < L_; t++) s = fmaf(lam, s, x[base + (size_t)t * D_]);
    g_carry[(b * NCH_ + c) * D_ + d] = s;
}

// Phase B: sequential combine across chunks (batched loads for MLP)
__global__ __launch_bounds__(256) void k_scan_combine() {
    int idx = blockIdx.x * blockDim.x + threadIdx.x;   // [0, B*D)
    int b = idx / D_;
    int d = idx % D_;
    float lam = g_lam[d >> 6];
    float lamL = pow_int(lam, L_);
    int base = b * NCH_ * D_ + d;

    float v[NCH_];
    #pragma unroll
    for (int c = 0; c < NCH_; c++) v[c] = g_carry[base + c * D_];
    float P = 0.0f;
    #pragma unroll
    for (int c = 0; c < NCH_; c++) { P = fmaf(lamL, P, v[c]); v[c] = P; }
    #pragma unroll
    for (int c = 0; c < NCH_; c++) g_carry[base + c * D_] = v[c];
}

// Phase C (fused): re-scan chunk with global carry, scale by c_h, RMSNorm,
// write fp16. One block per (b, chunk), 1024 threads, 32-token halves.
#define SNORM_SMEM (32 * 1024 * 4 + 256)
__global__ __launch_bounds__(1024) void k_scan_norm(const float* __restrict__ x,
                                                    const float* __restrict__ norm_weight) {
    extern __shared__ float sv[];                    // [32][1024]
    float* s_rstd = sv + 32 * 1024;                  // [32]
    int blk = blockIdx.x;
    int b = blk / NCH_;
    int c = blk % NCH_;
    int d = threadIdx.x;
    int lane = d & 31, wrp = d >> 5;
    float lam = g_lam[d >> 6];
    float ch  = g_c[d >> 6];
    float nw  = norm_weight[d];

    float s = (c > 0) ? g_carry[(b * NCH_ + (c - 1)) * D_ + d] : 0.0f;
    size_t xbase = (size_t)(b * N_ + c * L_) * D_ + d;

    #pragma unroll
    for (int half = 0; half < 2; half++) {
        #pragma unroll 8
        for (int t = 0; t < 32; t++) {
            s = fmaf(lam, s, x[xbase + (size_t)(half * 32 + t) * D_]);
            sv[t * 1024 + d] = s * ch;
        }
        __syncthreads();
        {
            float ss = 0.0f;
            const float* row = sv + wrp * 1024;
            #pragma unroll
            for (int j = 0; j < 32; j++) {
                float vv = row[lane + 32 * j];
                ss = fmaf(vv, vv, ss);
            }
            #pragma unroll
            for (int o = 16; o > 0; o >>= 1) ss += __shfl_xor_sync(0xFFFFFFFFu, ss, o);
            if (lane == 0) s_rstd[wrp] = rsqrtf(ss * (1.0f / (float)D_) + 1e-6f);
        }
        __syncthreads();
        int tok0 = (b * N_ + c * L_ + half * 32);
        #pragma unroll 4
        for (int t = 0; t < 32; t++) {
            float a = sv[t * 1024 + d] * s_rstd[t] * nw;
            float a1 = __shfl_down_sync(0xFFFFFFFFu, a, 1);
            if (!(d & 1)) {
                __half2 p = __floats2half2_rn(a, a1);
                *(__half2*)&g_a[(size_t)(tok0 + t) * D_ + d] = p;
            }
        }
        __syncthreads();
    }
}

__global__ __launch_bounds__(256) void k_prep_w(const float* __restrict__ w) {
    int idx = blockIdx.x * blockDim.x + threadIdx.x;
    size_t off = (size_t)idx * 4;
    float4 v = *(const float4*)&w[off];
    __half h0 = __float2half_rn(v.x), h1 = __float2half_rn(v.y);
    __half h2 = __float2half_rn(v.z), h3 = __float2half_rn(v.w);
    __half l0 = __float2half_rn(v.x - __half2float(h0));
    __half l1 = __float2half_rn(v.y - __half2float(h1));
    __half l2 = __float2half_rn(v.z - __half2float(h2));
    __half l3 = __float2half_rn(v.w - __half2float(h3));
    __half2 ph0; ph0.x = h0; ph0.y = h1;
    __half2 ph1; ph1.x = h2; ph1.y = h3;
    __half2 pl0; pl0.x = l0; pl0.y = l1;
    __half2 pl1; pl1.x = l2; pl1.y = l3;
    *(__half2*)&g_w_hi[off]     = ph0;
    *(__half2*)&g_w_hi[off + 2] = ph1;
    *(__half2*)&g_w_lo[off]     = pl0;
    *(__half2*)&g_w_lo[off + 2] = pl1;
}

// ============================ HMMA GEMM ============================
// C = A * (Whi + Wlo)^T. CTA 128x128, BK=64, 8 warps (4m x 2n), warp 32x64.
// STG=2 x 48KB stages -> 96KB/CTA -> 2 CTAs per SM.
#define GM 128
#define GN 128
#define KS 64
#define STG 2
#define NITER 16
#define TILE_B 16384                            // one 128x64 fp16 tile
#define STAGE_BYTES (3 * TILE_B)                // A, Whi, Wlo = 48KB
#define SMEM_GEMM_TOTAL (STG * STAGE_BYTES)     // 96KB

#define SMEM_SWZ(off) ((off) ^ (((off) >> 3) & 0x70))

__device__ __forceinline__ void load_stage(uint32_t smem_base, int round, int bm, int bn, int tid) {
    int k0 = round * KS;
    uint32_t st = smem_base + (round & 1) * STAGE_BYTES;
    #pragma unroll
    for (int i = 0; i < 12; i++) {
        int idx = i * 256 + tid;               // [0, 3072)
        int tile = idx >> 10;                  // 0:A 1:Whi 2:Wlo
        int c = idx & 1023;
        int r = c >> 3, kc = c & 7;
        const __half* src;
        int row;
        if (tile == 0)      { src = g_a;    row = bm + r; }
        else if (tile == 1) { src = g_w_hi; row = bn + r; }
        else                { src = g_w_lo; row = bn + r; }
        const __half* g = src + (size_t)row * D_ + k0 + kc * 8;
        CP_ASYNC16(st + tile * TILE_B + SMEM_SWZ(r * 128 + kc * 16), g);
    }
}

__global__ __launch_bounds__(256, 2) void k_gemm_mma(float* __restrict__ C) {
    extern __shared__ char smem[];
    uint32_t sb = smem_u32(smem);
    const int tid  = threadIdx.x;
    const int wid  = tid >> 5;
    const int lane = tid & 31;
    const int wm   = wid >> 1;          // 0..3 (M)
    const int wn   = wid & 1;           // 0..1 (N)
    const int bm   = blockIdx.y * GM;
    const int bn   = blockIdx.x * GN;

    const int t7 = lane & 7;
    const int q  = lane >> 3;
    // A x4 matrices: (m0,k0),(m+8,k0),(m0,k8),(m+8,k8)
    const int a_row = wm * 32 + (q & 1) * 8 + t7;
    const int a_cq  = q >> 1;
    // B x4 matrices: (n0,k0),(n0,k8),(n+8,k0),(n+8,k8)
    const int b_row = wn * 64 + (q >> 1) * 8 + t7;
    const int b_cq  = q & 1;

    float acc[2][8][4];
    #pragma unroll
    for (int im = 0; im < 2; im++)
        #pragma unroll
        for (int j = 0; j < 8; j++)
            #pragma unroll
            for (int e = 0; e < 4; e++) acc[im][j][e] = 0.0f;

    load_stage(sb, 0, bm, bn, tid);
    CP_COMMIT();

    for (int i = 0; i < NITER; i++) {
        int j = i + 1;
        if (j < NITER) load_stage(sb, j, bm, bn, tid);
        CP_COMMIT();
        CP_WAIT1();                    // stage i resident
        __syncthreads();

        uint32_t st = sb + (i & 1) * STAGE_BYTES;
        #pragma unroll
        for (int ks = 0; ks < 4; ks++) {
            uint32_t af[2][4];
            #pragma unroll
            for (int im = 0; im < 2; im++) {
                uint32_t ro = (a_row + im * 16) * 128 + (((ks * 2 + a_cq) ^ t7) << 4);
                LDSM4(af[im][0], af[im][1], af[im][2], af[im][3], st + ro);
            }
            uint32_t bf[8][2];
            // --- Whi product ---
            #pragma unroll
            for (int jj = 0; jj < 4; jj++) {
                uint32_t ro = (b_row + jj * 16) * 128 + (((ks * 2 + b_cq) ^ t7) << 4);
                LDSM4(bf[2*jj][0], bf[2*jj][1], bf[2*jj+1][0], bf[2*jj+1][1],
                      st + TILE_B + ro);
            }
            #pragma unroll
            for (int im = 0; im < 2; im++)
                #pragma unroll
                for (int jt = 0; jt < 8; jt++)
                    MMA_F16(acc[im][jt], af[im], bf[jt]);
            // --- Wlo product (reuse bf regs) ---
            #pragma unroll
            for (int jj = 0; jj < 4; jj++) {
                uint32_t ro = (b_row + jj * 16) * 128 + (((ks * 2 + b_cq) ^ t7) << 4);
                LDSM4(bf[2*jj][0], bf[2*jj][1], bf[2*jj+1][0], bf[2*jj+1][1],
                      st + 2 * TILE_B + ro);
            }
            #pragma unroll
            for (int im = 0; im < 2; im++)
                #pragma unroll
                for (int jt = 0; jt < 8; jt++)
                    MMA_F16(acc[im][jt], af[im], bf[jt]);
        }
        __syncthreads();               // all warps done with stage i before overwrite
    }

    #pragma unroll
    for (int im = 0; im < 2; im++) {
        int r0 = bm + wm * 32 + im * 16 + (lane >> 2);
        #pragma unroll
        for (int jt = 0; jt < 8; jt++) {
            int c = bn + wn * 64 + jt * 8 + (lane & 3) * 2;
            *(float2*)&C[(size_t)r0 * D_ + c]       = make_float2(acc[im][jt][0], acc[im][jt][1]);
            *(float2*)&C[(size_t)(r0 + 8) * D_ + c] = make_float2(acc[im][jt][2], acc[im][jt][3]);
        }
    }
}

// ============================ launch ============================
extern "C" void kernel_launch(void* const* d_in, const int* in_sizes, int n_in,
                              void* d_out, int out_size) {
    const float* x           = (const float*)d_in[0];
    const float* q           = (const float*)d_in[1];
    const float* k           = (const float*)d_in[2];
    const float* log_decay   = (const float*)d_in[3];
    const float* norm_weight = (const float*)d_in[4];
    const float* o_w         = (const float*)d_in[5];
    float* out = (float*)d_out;

    k_init<<<1, 32>>>(q, k, log_decay);
    k_prep_w<<<(D_ * D_ / 4) / 256, 256>>>(o_w);
    k_scan_carries<<<B_ * NCH_, 1024>>>(x);
    k_scan_combine<<<(B_ * D_) / 256, 256>>>();

    cudaFuncSetAttribute(k_scan_norm, cudaFuncAttributeMaxDynamicSharedMemorySize, SNORM_SMEM);
    k_scan_norm<<<B_ * NCH_, 1024, SNORM_SMEM>>>(x, norm_weight);

    cudaFuncSetAttribute(k_gemm_mma, cudaFuncAttributeMaxDynamicSharedMemorySize,
                         SMEM_GEMM_TOTAL);
    dim3 grid(D_ / GN, M_ / GM);
    k_gemm_mma<<<grid, 256, SMEM_GEMM_TOTAL>>>(out);
}

// round 8
// speedup vs baseline: 1.5949x; 1.4841x over previous
#include <cuda_runtime.h>
#include <cuda_fp16.h>
#include <cstdint>

// Problem constants
#define B_   4
#define N_   4096
#define D_   1024
#define H_   16
#define DH_  64
#define L_   64
#define NCH_ (N_ / L_)
#define M_   (B_ * N_)           // 16384 tokens

// Scratch (__device__ globals; no allocation allowed)
__device__ float g_carry[B_ * NCH_ * D_];
__device__ float g_lam[H_];
__device__ float g_c[H_];
__device__ __half g_a[M_ * D_];              // fp16 activations (post-norm)
__device__ __half g_w[D_ * D_];              // o_w fp16

__device__ __forceinline__ float pow_int(float base, int e) {
    float p = 1.0f, b = base;
    while (e) { if (e & 1) p *= b; b *= b; e >>= 1; }
    return p;
}

__device__ __forceinline__ uint32_t smem_u32(const void* p) {
    uint32_t a;
    asm("{ .reg .u64 t; cvta.to.shared.u64 t, %1; cvt.u32.u64 %0, t; }" : "=r"(a) : "l"(p));
    return a;
}

#define CP_ASYNC16(dst, src) \
    asm volatile("cp.async.cg.shared.global [%0], [%1], 16;" :: "r"(dst), "l"(src) : "memory")
#define CP_COMMIT() asm volatile("cp.async.commit_group;" ::: "memory")
#define CP_WAIT2()  asm volatile("cp.async.wait_group 2;" ::: "memory")

#define LDSM4(r0, r1, r2, r3, addr) \
    asm volatile("ldmatrix.sync.aligned.m8n8.x4.shared.b16 {%0,%1,%2,%3}, [%4];" \
                 : "=r"(r0), "=r"(r1), "=r"(r2), "=r"(r3) : "r"(addr))

#define MMA_F16(d, a, b) \
    asm volatile("mma.sync.aligned.m16n8k16.row.col.f32.f16.f16.f32 " \
                 "{%0,%1,%2,%3}, {%4,%5,%6,%7}, {%8,%9}, {%0,%1,%2,%3};" \
                 : "+f"((d)[0]), "+f"((d)[1]), "+f"((d)[2]), "+f"((d)[3]) \
                 : "r"((a)[0]), "r"((a)[1]), "r"((a)[2]), "r"((a)[3]), \
                   "r"((b)[0]), "r"((b)[1]))

// ============================ scan phases ============================
__global__ void k_init(const float* __restrict__ q, const float* __restrict__ k,
                       const float* __restrict__ log_decay) {
    int h = threadIdx.x;
    if (h >= H_) return;
    float a = log_decay[h];
    g_lam[h] = 1.0f / (1.0f + expf(-a));
    float c = 0.0f;
    const float* qh = q + h * DH_;
    const float* kh = k + h * DH_;
    #pragma unroll 16
    for (int j = 0; j < DH_; j++) c += qh[j] * kh[j];
    g_c[h] = c;
}

// Phase A: per-chunk carries only
__global__ __launch_bounds__(1024) void k_scan_carries(const float* __restrict__ x) {
    int blk = blockIdx.x;
    int b = blk / NCH_;
    int c = blk % NCH_;
    int d = threadIdx.x;
    float lam = g_lam[d >> 6];
    size_t base = (size_t)(b * N_ + c * L_) * D_ + d;
    float s = 0.0f;
    #pragma unroll 8
    for (int t = 0; t < L_; t++) s = fmaf(lam, s, x[base + (size_t)t * D_]);
    g_carry[(b * NCH_ + c) * D_ + d] = s;
}

// Phase B: sequential combine across chunks (batched loads for MLP)
__global__ __launch_bounds__(256) void k_scan_combine() {
    int idx = blockIdx.x * blockDim.x + threadIdx.x;   // [0, B*D)
    int b = idx / D_;
    int d = idx % D_;
    float lam = g_lam[d >> 6];
    float lamL = pow_int(lam, L_);
    int base = b * NCH_ * D_ + d;

    float v[NCH_];
    #pragma unroll
    for (int c = 0; c < NCH_; c++) v[c] = g_carry[base + c * D_];
    float P = 0.0f;
    #pragma unroll
    for (int c = 0; c < NCH_; c++) { P = fmaf(lamL, P, v[c]); v[c] = P; }
    #pragma unroll
    for (int c = 0; c < NCH_; c++) g_carry[base + c * D_] = v[c];
}

// Phase C (fused): re-scan chunk with global carry, scale by c_h, RMSNorm,
// write fp16. One block per (b, chunk), 1024 threads, 32-token halves.
#define SNORM_SMEM (32 * 1024 * 4 + 256)
__global__ __launch_bounds__(1024) void k_scan_norm(const float* __restrict__ x,
                                                    const float* __restrict__ norm_weight) {
    extern __shared__ float sv[];                    // [32][1024]
    float* s_rstd = sv + 32 * 1024;                  // [32]
    int blk = blockIdx.x;
    int b = blk / NCH_;
    int c = blk % NCH_;
    int d = threadIdx.x;
    int lane = d & 31, wrp = d >> 5;
    float lam = g_lam[d >> 6];
    float ch  = g_c[d >> 6];
    float nw  = norm_weight[d];

    float s = (c > 0) ? g_carry[(b * NCH_ + (c - 1)) * D_ + d] : 0.0f;
    size_t xbase = (size_t)(b * N_ + c * L_) * D_ + d;

    #pragma unroll
    for (int half = 0; half < 2; half++) {
        #pragma unroll 8
        for (int t = 0; t < 32; t++) {
            s = fmaf(lam, s, x[xbase + (size_t)(half * 32 + t) * D_]);
            sv[t * 1024 + d] = s * ch;
        }
        __syncthreads();
        {
            float ss = 0.0f;
            const float* row = sv + wrp * 1024;
            #pragma unroll
            for (int j = 0; j < 32; j++) {
                float vv = row[lane + 32 * j];
                ss = fmaf(vv, vv, ss);
            }
            #pragma unroll
            for (int o = 16; o > 0; o >>= 1) ss += __shfl_xor_sync(0xFFFFFFFFu, ss, o);
            if (lane == 0) s_rstd[wrp] = rsqrtf(ss * (1.0f / (float)D_) + 1e-6f);
        }
        __syncthreads();
        int tok0 = (b * N_ + c * L_ + half * 32);
        #pragma unroll 4
        for (int t = 0; t < 32; t++) {
            float a = sv[t * 1024 + d] * s_rstd[t] * nw;
            float a1 = __shfl_down_sync(0xFFFFFFFFu, a, 1);
            if (!(d & 1)) {
                __half2 p = __floats2half2_rn(a, a1);
                *(__half2*)&g_a[(size_t)(tok0 + t) * D_ + d] = p;
            }
        }
        __syncthreads();
    }
}

__global__ __launch_bounds__(256) void k_prep_w(const float* __restrict__ w) {
    int idx = blockIdx.x * blockDim.x + threadIdx.x;
    size_t off = (size_t)idx * 4;
    float4 v = *(const float4*)&w[off];
    __half2 p0 = __floats2half2_rn(v.x, v.y);
    __half2 p1 = __floats2half2_rn(v.z, v.w);
    *(__half2*)&g_w[off]     = p0;
    *(__half2*)&g_w[off + 2] = p1;
}

// ============================ HMMA GEMM ============================
// C = A * W^T (single fp16 product, fp32 accum). CTA 128x128, BK=64,
// 8 warps (4m x 2n), warp 32x64. STG=3 x 32KB -> 96KB/CTA -> occ=2.
#define GM 128
#define GN 128
#define KS 64
#define STG 3
#define NITER 16
#define TILE_B 16384                            // one 128x64 fp16 tile
#define STAGE_BYTES (2 * TILE_B)                // A + W = 32KB
#define SMEM_GEMM_TOTAL (STG * STAGE_BYTES)     // 96KB

#define SMEM_SWZ(off) ((off) ^ (((off) >> 3) & 0x70))

__device__ __forceinline__ void load_stage(uint32_t smem_base, int round, int bm, int bn, int tid) {
    int k0 = round * KS;
    uint32_t st = smem_base + (round % STG) * STAGE_BYTES;
    #pragma unroll
    for (int i = 0; i < 8; i++) {
        int idx = i * 256 + tid;               // [0, 2048)
        int tile = idx >> 10;                  // 0:A 1:W
        int c = idx & 1023;
        int r = c >> 3, kc = c & 7;
        const __half* src = tile ? g_w : g_a;
        int row = (tile ? bn : bm) + r;
        const __half* g = src + (size_t)row * D_ + k0 + kc * 8;
        CP_ASYNC16(st + tile * TILE_B + SMEM_SWZ(r * 128 + kc * 16), g);
    }
}

__global__ __launch_bounds__(256, 2) void k_gemm_mma(float* __restrict__ C) {
    extern __shared__ char smem[];
    uint32_t sb = smem_u32(smem);
    const int tid  = threadIdx.x;
    const int wid  = tid >> 5;
    const int lane = tid & 31;
    const int wm   = wid >> 1;          // 0..3 (M)
    const int wn   = wid & 1;           // 0..1 (N)
    const int bm   = blockIdx.y * GM;
    const int bn   = blockIdx.x * GN;

    const int t7 = lane & 7;
    const int q  = lane >> 3;
    // A x4 matrices: (m0,k0),(m+8,k0),(m0,k8),(m+8,k8)
    const int a_row = wm * 32 + (q & 1) * 8 + t7;
    const int a_cq  = q >> 1;
    // B x4 matrices: (n0,k0),(n0,k8),(n+8,k0),(n+8,k8)
    const int b_row = wn * 64 + (q >> 1) * 8 + t7;
    const int b_cq  = q & 1;

    float acc[2][8][4];
    #pragma unroll
    for (int im = 0; im < 2; im++)
        #pragma unroll
        for (int j = 0; j < 8; j++)
            #pragma unroll
            for (int e = 0; e < 4; e++) acc[im][j][e] = 0.0f;

    load_stage(sb, 0, bm, bn, tid); CP_COMMIT();
    load_stage(sb, 1, bm, bn, tid); CP_COMMIT();

    for (int i = 0; i < NITER; i++) {
        int j = i + 2;
        if (j < NITER) load_stage(sb, j, bm, bn, tid);
        CP_COMMIT();
        CP_WAIT2();                    // stage i resident
        __syncthreads();

        uint32_t st = sb + (i % STG) * STAGE_BYTES;
        #pragma unroll
        for (int ks = 0; ks < 4; ks++) {
            uint32_t af[2][4];
            #pragma unroll
            for (int im = 0; im < 2; im++) {
                uint32_t ro = (a_row + im * 16) * 128 + (((ks * 2 + a_cq) ^ t7) << 4);
                LDSM4(af[im][0], af[im][1], af[im][2], af[im][3], st + ro);
            }
            uint32_t bf[8][2];
            #pragma unroll
            for (int jj = 0; jj < 4; jj++) {
                uint32_t ro = (b_row + jj * 16) * 128 + (((ks * 2 + b_cq) ^ t7) << 4);
                LDSM4(bf[2*jj][0], bf[2*jj][1], bf[2*jj+1][0], bf[2*jj+1][1],
                      st + TILE_B + ro);
            }
            #pragma unroll
            for (int im = 0; im < 2; im++)
                #pragma unroll
                for (int jt = 0; jt < 8; jt++)
                    MMA_F16(acc[im][jt], af[im], bf[jt]);
        }
        __syncthreads();               // all warps done with stage i before overwrite
    }

    #pragma unroll
    for (int im = 0; im < 2; im++) {
        int r0 = bm + wm * 32 + im * 16 + (lane >> 2);
        #pragma unroll
        for (int jt = 0; jt < 8; jt++) {
            int c = bn + wn * 64 + jt * 8 + (lane & 3) * 2;
            *(float2*)&C[(size_t)r0 * D_ + c]       = make_float2(acc[im][jt][0], acc[im][jt][1]);
            *(float2*)&C[(size_t)(r0 + 8) * D_ + c] = make_float2(acc[im][jt][2], acc[im][jt][3]);
        }
    }
}

// ============================ launch ============================
extern "C" void kernel_launch(void* const* d_in, const int* in_sizes, int n_in,
                              void* d_out, int out_size) {
    const float* x           = (const float*)d_in[0];
    const float* q           = (const float*)d_in[1];
    const float* k           = (const float*)d_in[2];
    const float* log_decay   = (const float*)d_in[3];
    const float* norm_weight = (const float*)d_in[4];
    const float* o_w         = (const float*)d_in[5];
    float* out = (float*)d_out;

    k_init<<<1, 32>>>(q, k, log_decay);
    k_prep_w<<<(D_ * D_ / 4) / 256, 256>>>(o_w);
    k_scan_carries<<<B_ * NCH_, 1024>>>(x);
    k_scan_combine<<<(B_ * D_) / 256, 256>>>();

    cudaFuncSetAttribute(k_scan_norm, cudaFuncAttributeMaxDynamicSharedMemorySize, SNORM_SMEM);
    k_scan_norm<<<B_ * NCH_, 1024, SNORM_SMEM>>>(x, norm_weight);

    cudaFuncSetAttribute(k_gemm_mma, cudaFuncAttributeMaxDynamicSharedMemorySize,
                         SMEM_GEMM_TOTAL);
    dim3 grid(D_ / GN, M_ / GM);
    k_gemm_mma<<<grid, 256, SMEM_GEMM_TOTAL>>>(out);
}

// round 9
// speedup vs baseline: 1.6398x; 1.0281x over previous
#include <cuda_runtime.h>
#include <cuda_fp16.h>
#include <cstdint>

// Problem constants
#define B_   4
#define N_   4096
#define D_   1024
#define H_   16
#define DH_  64
#define L_   64
#define NCH_ (N_ / L_)
#define M_   (B_ * N_)           // 16384 tokens

// Scratch (__device__ globals; no allocation allowed)
__device__ float g_carry[B_ * NCH_ * D_];
__device__ float g_lam[H_];
__device__ float g_c[H_];
__device__ __half g_a[M_ * D_];              // fp16 activations (post-norm)
__device__ __half g_w[D_ * D_];              // o_w fp16

__device__ __forceinline__ float pow_int(float base, int e) {
    float p = 1.0f, b = base;
    while (e) { if (e & 1) p *= b; b *= b; e >>= 1; }
    return p;
}

__device__ __forceinline__ uint32_t smem_u32(const void* p) {
    uint32_t a;
    asm("{ .reg .u64 t; cvta.to.shared.u64 t, %1; cvt.u32.u64 %0, t; }" : "=r"(a) : "l"(p));
    return a;
}

#define CP_ASYNC16(dst, src) \
    asm volatile("cp.async.cg.shared.global [%0], [%1], 16;" :: "r"(dst), "l"(src) : "memory")
#define CP_COMMIT() asm volatile("cp.async.commit_group;" ::: "memory")
#define CP_WAIT1()  asm volatile("cp.async.wait_group 1;" ::: "memory")

#define LDSM4(r0, r1, r2, r3, addr) \
    asm volatile("ldmatrix.sync.aligned.m8n8.x4.shared.b16 {%0,%1,%2,%3}, [%4];" \
                 : "=r"(r0), "=r"(r1), "=r"(r2), "=r"(r3) : "r"(addr))

#define MMA_F16(d, a, b) \
    asm volatile("mma.sync.aligned.m16n8k16.row.col.f32.f16.f16.f32 " \
                 "{%0,%1,%2,%3}, {%4,%5,%6,%7}, {%8,%9}, {%0,%1,%2,%3};" \
                 : "+f"((d)[0]), "+f"((d)[1]), "+f"((d)[2]), "+f"((d)[3]) \
                 : "r"((a)[0]), "r"((a)[1]), "r"((a)[2]), "r"((a)[3]), \
                   "r"((b)[0]), "r"((b)[1]))

// ============================ scan phases ============================
__global__ void k_init(const float* __restrict__ q, const float* __restrict__ k,
                       const float* __restrict__ log_decay) {
    int h = threadIdx.x;
    if (h >= H_) return;
    float a = log_decay[h];
    g_lam[h] = 1.0f / (1.0f + expf(-a));
    float c = 0.0f;
    const float* qh = q + h * DH_;
    const float* kh = k + h * DH_;
    #pragma unroll 16
    for (int j = 0; j < DH_; j++) c += qh[j] * kh[j];
    g_c[h] = c;
}

// Phase A: per-chunk carries only
__global__ __launch_bounds__(1024) void k_scan_carries(const float* __restrict__ x) {
    int blk = blockIdx.x;
    int b = blk / NCH_;
    int c = blk % NCH_;
    int d = threadIdx.x;
    float lam = g_lam[d >> 6];
    size_t base = (size_t)(b * N_ + c * L_) * D_ + d;
    float s = 0.0f;
    #pragma unroll 8
    for (int t = 0; t < L_; t++) s = fmaf(lam, s, x[base + (size_t)t * D_]);
    g_carry[(b * NCH_ + c) * D_ + d] = s;
}

// Phase B: sequential combine across chunks (batched loads for MLP)
__global__ __launch_bounds__(256) void k_scan_combine() {
    int idx = blockIdx.x * blockDim.x + threadIdx.x;   // [0, B*D)
    int b = idx / D_;
    int d = idx % D_;
    float lam = g_lam[d >> 6];
    float lamL = pow_int(lam, L_);
    int base = b * NCH_ * D_ + d;

    float v[NCH_];
    #pragma unroll
    for (int c = 0; c < NCH_; c++) v[c] = g_carry[base + c * D_];
    float P = 0.0f;
    #pragma unroll
    for (int c = 0; c < NCH_; c++) { P = fmaf(lamL, P, v[c]); v[c] = P; }
    #pragma unroll
    for (int c = 0; c < NCH_; c++) g_carry[base + c * D_] = v[c];
}

// Phase C (fused): re-scan chunk with global carry, scale by c_h, RMSNorm,
// write fp16. One block per (b, chunk), 1024 threads, 32-token halves.
#define SNORM_SMEM (32 * 1024 * 4 + 256)
__global__ __launch_bounds__(1024) void k_scan_norm(const float* __restrict__ x,
                                                    const float* __restrict__ norm_weight) {
    extern __shared__ float sv[];                    // [32][1024]
    float* s_rstd = sv + 32 * 1024;                  // [32]
    int blk = blockIdx.x;
    int b = blk / NCH_;
    int c = blk % NCH_;
    int d = threadIdx.x;
    int lane = d & 31, wrp = d >> 5;
    float lam = g_lam[d >> 6];
    float ch  = g_c[d >> 6];
    float nw  = norm_weight[d];

    float s = (c > 0) ? g_carry[(b * NCH_ + (c - 1)) * D_ + d] : 0.0f;
    size_t xbase = (size_t)(b * N_ + c * L_) * D_ + d;

    #pragma unroll
    for (int half = 0; half < 2; half++) {
        #pragma unroll 8
        for (int t = 0; t < 32; t++) {
            s = fmaf(lam, s, x[xbase + (size_t)(half * 32 + t) * D_]);
            sv[t * 1024 + d] = s * ch;
        }
        __syncthreads();
        {
            float ss = 0.0f;
            const float* row = sv + wrp * 1024;
            #pragma unroll
            for (int j = 0; j < 32; j++) {
                float vv = row[lane + 32 * j];
                ss = fmaf(vv, vv, ss);
            }
            #pragma unroll
            for (int o = 16; o > 0; o >>= 1) ss += __shfl_xor_sync(0xFFFFFFFFu, ss, o);
            if (lane == 0) s_rstd[wrp] = rsqrtf(ss * (1.0f / (float)D_) + 1e-6f);
        }
        __syncthreads();
        int tok0 = (b * N_ + c * L_ + half * 32);
        #pragma unroll 4
        for (int t = 0; t < 32; t++) {
            float a = sv[t * 1024 + d] * s_rstd[t] * nw;
            float a1 = __shfl_down_sync(0xFFFFFFFFu, a, 1);
            if (!(d & 1)) {
                __half2 p = __floats2half2_rn(a, a1);
                *(__half2*)&g_a[(size_t)(tok0 + t) * D_ + d] = p;
            }
        }
        __syncthreads();
    }
}

__global__ __launch_bounds__(256) void k_prep_w(const float* __restrict__ w) {
    int idx = blockIdx.x * blockDim.x + threadIdx.x;
    size_t off = (size_t)idx * 4;
    float4 v = *(const float4*)&w[off];
    __half2 p0 = __floats2half2_rn(v.x, v.y);
    __half2 p1 = __floats2half2_rn(v.z, v.w);
    *(__half2*)&g_w[off]     = p0;
    *(__half2*)&g_w[off + 2] = p1;
}

// ============================ HMMA GEMM ============================
// C = A * W^T (fp16 in, fp32 accum). CTA 128x128, BK=64, 8 warps (4m x 2n),
// warp 32x64. STG=3 x 32KB -> 96KB/CTA -> occ=2. One barrier per stage.
#define GM 128
#define GN 128
#define KS 64
#define STG 3
#define NITER 16
#define TILE_B 16384                            // one 128x64 fp16 tile
#define STAGE_BYTES (2 * TILE_B)                // A + W = 32KB
#define SMEM_GEMM_TOTAL (STG * STAGE_BYTES)     // 96KB

#define SMEM_SWZ(off) ((off) ^ (((off) >> 3) & 0x70))

__device__ __forceinline__ void load_stage(uint32_t smem_base, int round, int buf,
                                           int bm, int bn, int tid) {
    int k0 = round * KS;
    uint32_t st = smem_base + buf * STAGE_BYTES;
    #pragma unroll
    for (int i = 0; i < 8; i++) {
        int idx = i * 256 + tid;               // [0, 2048)
        int tile = idx >> 10;                  // 0:A 1:W
        int c = idx & 1023;
        int r = c >> 3, kc = c & 7;
        const __half* src = tile ? g_w : g_a;
        int row = (tile ? bn : bm) + r;
        const __half* g = src + (size_t)row * D_ + k0 + kc * 8;
        CP_ASYNC16(st + tile * TILE_B + SMEM_SWZ(r * 128 + kc * 16), g);
    }
}

__global__ __launch_bounds__(256, 2) void k_gemm_mma(float* __restrict__ C) {
    extern __shared__ char smem[];
    uint32_t sb = smem_u32(smem);
    const int tid  = threadIdx.x;
    const int wid  = tid >> 5;
    const int lane = tid & 31;
    const int wm   = wid >> 1;          // 0..3 (M)
    const int wn   = wid & 1;           // 0..1 (N)
    const int bm   = blockIdx.y * GM;
    const int bn   = blockIdx.x * GN;

    const int t7 = lane & 7;
    const int q  = lane >> 3;
    // A x4 matrices: (m0,k0),(m+8,k0),(m0,k8),(m+8,k8)
    const int a_row = wm * 32 + (q & 1) * 8 + t7;
    const int a_cq  = q >> 1;
    // B x4 matrices: (n0,k0),(n0,k8),(n+8,k0),(n+8,k8)
    const int b_row = wn * 64 + (q >> 1) * 8 + t7;
    const int b_cq  = q & 1;

    float acc[2][8][4];
    #pragma unroll
    for (int im = 0; im < 2; im++)
        #pragma unroll
        for (int j = 0; j < 8; j++)
            #pragma unroll
            for (int e = 0; e < 4; e++) acc[im][j][e] = 0.0f;

    load_stage(sb, 0, 0, bm, bn, tid); CP_COMMIT();
    load_stage(sb, 1, 1, bm, bn, tid); CP_COMMIT();

    int buf = 0;       // buffer holding stage i
    int lbuf = 2;      // buffer to fill with stage i+2
    for (int i = 0; i < NITER; i++) {
        CP_WAIT1();                    // stage i resident (leave i+1 pending)
        __syncthreads();               // also: all warps done reading buffer lbuf (stage i-1)

        int j = i + 2;
        if (j < NITER) load_stage(sb, j, lbuf, bm, bn, tid);
        CP_COMMIT();                   // empty commits in tail keep group counts uniform

        uint32_t st = sb + buf * STAGE_BYTES;
        #pragma unroll
        for (int ks = 0; ks < 4; ks++) {
            uint32_t af[2][4];
            #pragma unroll
            for (int im = 0; im < 2; im++) {
                uint32_t ro = (a_row + im * 16) * 128 + (((ks * 2 + a_cq) ^ t7) << 4);
                LDSM4(af[im][0], af[im][1], af[im][2], af[im][3], st + ro);
            }
            uint32_t bf[8][2];
            #pragma unroll
            for (int jj = 0; jj < 4; jj++) {
                uint32_t ro = (b_row + jj * 16) * 128 + (((ks * 2 + b_cq) ^ t7) << 4);
                LDSM4(bf[2*jj][0], bf[2*jj][1], bf[2*jj+1][0], bf[2*jj+1][1],
                      st + TILE_B + ro);
            }
            #pragma unroll
            for (int im = 0; im < 2; im++)
                #pragma unroll
                for (int jt = 0; jt < 8; jt++)
                    MMA_F16(acc[im][jt], af[im], bf[jt]);
        }

        buf  = (buf == STG - 1) ? 0 : buf + 1;
        lbuf = (lbuf == STG - 1) ? 0 : lbuf + 1;
    }

    #pragma unroll
    for (int im = 0; im < 2; im++) {
        int r0 = bm + wm * 32 + im * 16 + (lane >> 2);
        #pragma unroll
        for (int jt = 0; jt < 8; jt++) {
            int c = bn + wn * 64 + jt * 8 + (lane & 3) * 2;
            *(float2*)&C[(size_t)r0 * D_ + c]       = make_float2(acc[im][jt][0], acc[im][jt][1]);
            *(float2*)&C[(size_t)(r0 + 8) * D_ + c] = make_float2(acc[im][jt][2], acc[im][jt][3]);
        }
    }
}

// ============================ launch ============================
extern "C" void kernel_launch(void* const* d_in, const int* in_sizes, int n_in,
                              void* d_out, int out_size) {
    const float* x           = (const float*)d_in[0];
    const float* q           = (const float*)d_in[1];
    const float* k           = (const float*)d_in[2];
    const float* log_decay   = (const float*)d_in[3];
    const float* norm_weight = (const float*)d_in[4];
    const float* o_w         = (const float*)d_in[5];
    float* out = (float*)d_out;

    k_init<<<1, 32>>>(q, k, log_decay);
    k_prep_w<<<(D_ * D_ / 4) / 256, 256>>>(o_w);
    k_scan_carries<<<B_ * NCH_, 1024>>>(x);
    k_scan_combine<<<(B_ * D_) / 256, 256>>>();

    cudaFuncSetAttribute(k_scan_norm, cudaFuncAttributeMaxDynamicSharedMemorySize, SNORM_SMEM);
    k_scan_norm<<<B_ * NCH_, 1024, SNORM_SMEM>>>(x, norm_weight);

    cudaFuncSetAttribute(k_gemm_mma, cudaFuncAttributeMaxDynamicSharedMemorySize,
                         SMEM_GEMM_TOTAL);
    dim3 grid(D_ / GN, M_ / GM);
    k_gemm_mma<<<grid, 256, SMEM_GEMM_TOTAL>>>(out);
}